// round 3
// baseline (speedup 1.0000x reference)
#include <cuda_runtime.h>
#include <cuda_bf16.h>
#include <math.h>

// Problem dims
#define T_ 32
#define B_ 64
#define S_ 64
#define D_ 1024
#define D4_ 4096
#define TB_ 2048   // T*B

// ---------------- scratch (device globals; no cudaMalloc allowed) ----------------
__device__ float g_x0[TB_ * D_];    // embedded input        8 MB
__device__ float g_xg[TB_ * D4_];   // precomputed gates    32 MB (reused per layer)
__device__ float g_x1[TB_ * D_];    // layer0 outputs        8 MB
__device__ float g_x2[TB_ * D_];    // layer1 outputs        8 MB
__device__ float g_c [B_ * D_];     // cell state           256 KB
__device__ float g_q [TB_ * D_];    // attention query       8 MB
__device__ float g_cat[TB_ * 2 * D_]; // [weighted, x]      16 MB

// ---------------- f32x2 helpers (Blackwell packed fp32) ----------------
__device__ __forceinline__ void fma2(unsigned long long& d,
                                     unsigned long long a,
                                     unsigned long long b)
{
    asm("fma.rn.f32x2 %0, %1, %2, %0;" : "+l"(d) : "l"(a), "l"(b));
}
__device__ __forceinline__ unsigned long long dup2(float a)
{
    unsigned long long r;
    asm("mov.b64 %0, {%1, %1};" : "=l"(r) : "r"(__float_as_uint(a)));
    return r;
}
__device__ __forceinline__ float pairsum(unsigned long long v)
{
    unsigned int lo, hi;
    asm("mov.b64 {%0, %1}, %2;" : "=r"(lo), "=r"(hi) : "l"(v));
    return __uint_as_float(lo) + __uint_as_float(hi);
}
__device__ __forceinline__ void unpack2(unsigned long long v, float& a, float& b)
{
    unsigned int lo, hi;
    asm("mov.b64 {%0, %1}, %2;" : "=r"(lo), "=r"(hi) : "l"(v));
    a = __uint_as_float(lo);
    b = __uint_as_float(hi);
}

// ---------------- embedding (padding_idx = 0) ----------------
__global__ void embed_kernel(const int* __restrict__ tok,
                             const float* __restrict__ emb,
                             float* __restrict__ x)
{
    int tb = blockIdx.x;          // 0..2047
    int t4 = threadIdx.x;         // 0..255 (float4 lanes, D/4 = 256)
    int tk = tok[tb];
    float4 v = make_float4(0.f, 0.f, 0.f, 0.f);
    if (tk != 0) v = ((const float4*)(emb + (size_t)tk * D_))[t4];
    ((float4*)(x + (size_t)tb * D_))[t4] = v;
}

// ---------------- SGEMM: C = A @ B^T (+epilogue), f32x2 inner ----------------
// A: (M,K) row-major, B: (N,K) row-major, C: (M,N) row-major.
// M,N multiples of 128; K multiple of 16.
// EPI: 0 = none, 1 = +bias1[n]+bias2[n], 2 = tanh
template<int EPI>
__global__ __launch_bounds__(256)
void sgemm_nt(const float* __restrict__ A, const float* __restrict__ Bm,
              float* __restrict__ C, int M, int N, int K,
              const float* __restrict__ bias1, const float* __restrict__ bias2)
{
    __shared__ float As[16][128];
    __shared__ float Bs[16][128];

    const int tid = threadIdx.x;
    const int bm = blockIdx.y * 128;
    const int bn = blockIdx.x * 128;
    const int tx = tid & 15, ty = tid >> 4;

    unsigned long long acc[8][4];   // [m][n-pair]: each holds (n2p, n2p+1)
#pragma unroll
    for (int i = 0; i < 8; i++)
#pragma unroll
        for (int j = 0; j < 4; j++) acc[i][j] = 0ULL;

    for (int k0 = 0; k0 < K; k0 += 16) {
        // load 128x16 tiles of A and B (transposed into smem)
#pragma unroll
        for (int i = 0; i < 2; i++) {
            int v = tid * 2 + i;        // 0..511 float4 id
            int row = v >> 2;
            int q = (v & 3) * 4;
            float4 a4 = *(const float4*)(A + (size_t)(bm + row) * K + k0 + q);
            As[q + 0][row] = a4.x; As[q + 1][row] = a4.y;
            As[q + 2][row] = a4.z; As[q + 3][row] = a4.w;
            float4 b4 = *(const float4*)(Bm + (size_t)(bn + row) * K + k0 + q);
            Bs[q + 0][row] = b4.x; Bs[q + 1][row] = b4.y;
            Bs[q + 2][row] = b4.z; Bs[q + 3][row] = b4.w;
        }
        __syncthreads();

#pragma unroll
        for (int kk = 0; kk < 16; kk++) {
            float a[8];
            *(float4*)(a)     = *(const float4*)&As[kk][ty * 8];
            *(float4*)(a + 4) = *(const float4*)&As[kk][ty * 8 + 4];
            ulonglong2 bq0 = *(const ulonglong2*)&Bs[kk][tx * 8];
            ulonglong2 bq1 = *(const ulonglong2*)&Bs[kk][tx * 8 + 4];
#pragma unroll
            for (int i = 0; i < 8; i++) {
                unsigned long long ad = dup2(a[i]);
                fma2(acc[i][0], ad, bq0.x);
                fma2(acc[i][1], ad, bq0.y);
                fma2(acc[i][2], ad, bq1.x);
                fma2(acc[i][3], ad, bq1.y);
            }
        }
        __syncthreads();
    }

#pragma unroll
    for (int i = 0; i < 8; i++) {
        int m = bm + ty * 8 + i;
        int n0 = bn + tx * 8;
        float v[8];
#pragma unroll
        for (int p = 0; p < 4; p++) unpack2(acc[i][p], v[2 * p], v[2 * p + 1]);
#pragma unroll
        for (int j = 0; j < 8; j++) {
            float x = v[j];
            if (EPI == 1) x += bias1[n0 + j] + bias2[n0 + j];
            if (EPI == 2) x = tanhf(x);
            v[j] = x;
        }
        *(float4*)(C + (size_t)m * N + n0)     = *(float4*)(v);
        *(float4*)(C + (size_t)m * N + n0 + 4) = *(float4*)(v + 4);
    }
}

// ---------------- fused LSTM step (smem-staged, f32x2) ----------------
// Block handles 8 output dims (d0..d0+7), all 4 gates, all 64 batches.
// Thread (ni = tid&7 -> dim, bi = tid>>3 -> 2 batches). grid=128, 256 threads.
// gates = xg_t + hprev @ whh^T; pointwise fully thread-local.
#define LCH 128          // k-chunk staged in smem
#define LPAD 132         // padded row stride (floats); 132*4 B is 16B-aligned

__global__ __launch_bounds__(256, 1)
void lstm_step(const float* __restrict__ xg_t,   // (B, 4D)
               const float* __restrict__ hprev,  // (B, D)
               const float* __restrict__ whh,    // (4D, D)
               float* __restrict__ c,            // (B, D) in-place
               float* __restrict__ hout)         // (B, D)
{
    __shared__ float hs[B_][LPAD];   // 64 x 132 floats  (33.8 KB)
    __shared__ float ws[32][LPAD];   // 32 x 132 floats  (16.9 KB)

    const int tid = threadIdx.x;
    const int ni = tid & 7;          // dim within block
    const int bi = tid >> 3;         // 0..31
    const int d0 = blockIdx.x << 3;
    const int d  = d0 + ni;
    const int b0 = bi << 1;          // 2 batches per thread

    unsigned long long acc[4][2];    // [gate][batch], k-paired partial sums
#pragma unroll
    for (int g = 0; g < 4; g++) { acc[g][0] = 0ULL; acc[g][1] = 0ULL; }

    for (int base = 0; base < D_; base += LCH) {
        __syncthreads();
        // stage h chunk: 64 rows x 32 float4
        for (int v = tid; v < B_ * (LCH / 4); v += 256) {
            int r = v >> 5, q = v & 31;
            *(float4*)&hs[r][q * 4] =
                *(const float4*)(hprev + (size_t)r * D_ + base + q * 4);
        }
        // stage w slice: rows r = g*8 + nn  -> whh row (g*1024 + d0 + nn)
        for (int v = tid; v < 32 * (LCH / 4); v += 256) {
            int r = v >> 5, q = v & 31;
            int g = r >> 3, nn = r & 7;
            *(float4*)&ws[r][q * 4] =
                *(const float4*)(whh + ((size_t)(g << 10) + d0 + nn) * D_ + base + q * 4);
        }
        __syncthreads();

#pragma unroll 2
        for (int kk = 0; kk < LCH; kk += 8) {
            ulonglong2 hv[2][2];
#pragma unroll
            for (int j = 0; j < 2; j++) {
                hv[j][0] = *(const ulonglong2*)&hs[b0 + j][kk];
                hv[j][1] = *(const ulonglong2*)&hs[b0 + j][kk + 4];
            }
            ulonglong2 wv[4][2];
#pragma unroll
            for (int g = 0; g < 4; g++) {
                wv[g][0] = *(const ulonglong2*)&ws[(g << 3) + ni][kk];
                wv[g][1] = *(const ulonglong2*)&ws[(g << 3) + ni][kk + 4];
            }
#pragma unroll
            for (int g = 0; g < 4; g++)
#pragma unroll
                for (int j = 0; j < 2; j++) {
                    fma2(acc[g][j], hv[j][0].x, wv[g][0].x);
                    fma2(acc[g][j], hv[j][0].y, wv[g][0].y);
                    fma2(acc[g][j], hv[j][1].x, wv[g][1].x);
                    fma2(acc[g][j], hv[j][1].y, wv[g][1].y);
                }
        }
    }

    // pointwise, fully thread-local
#pragma unroll
    for (int j = 0; j < 2; j++) {
        int b = b0 + j;
        float ig = pairsum(acc[0][j]) + xg_t[(size_t)b * D4_ + 0 * D_ + d];
        float fg = pairsum(acc[1][j]) + xg_t[(size_t)b * D4_ + 1 * D_ + d];
        float gg = pairsum(acc[2][j]) + xg_t[(size_t)b * D4_ + 2 * D_ + d];
        float og = pairsum(acc[3][j]) + xg_t[(size_t)b * D4_ + 3 * D_ + d];
        size_t idx = (size_t)b * D_ + d;
        float ci = c[idx];
        float i_ = 1.f / (1.f + __expf(-ig));
        float f_ = 1.f / (1.f + __expf(-fg));
        float o_ = 1.f / (1.f + __expf(-og));
        float cn = f_ * ci + i_ * tanhf(gg);
        float hn = o_ * tanhf(cn);
        c[idx] = cn;
        hout[idx] = hn;
    }
}

// ---------------- attention: scores + softmax + weighted + cat ----------------
// one block per (t,b); 256 threads
__global__ __launch_bounds__(256)
void attn_kernel(const float* __restrict__ q,      // (T*B, D)
                 const float* __restrict__ ctx,    // (S, B, D)
                 const float* __restrict__ x,      // (T*B, D)
                 float* __restrict__ cat,          // (T*B, 2D)
                 float* __restrict__ attn_out)     // (B, S), written at t=T-1
{
    const int b = blockIdx.x;
    const int t = blockIdx.y;
    const int tb = t * B_ + b;
    __shared__ float qs[D_];
    __shared__ float sc[S_];

    const int tid = threadIdx.x;
    const int warp = tid >> 5, lane = tid & 31;

    ((float4*)qs)[tid] = ((const float4*)(q + (size_t)tb * D_))[tid];
    __syncthreads();

#pragma unroll
    for (int si = 0; si < 8; si++) {
        int s = warp * 8 + si;
        const float4* crow = (const float4*)(ctx + (size_t)(s * B_ + b) * D_);
        float sum = 0.f;
#pragma unroll
        for (int i = 0; i < 8; i++) {
            float4 cv = crow[lane + 32 * i];
            float4 qv = ((const float4*)qs)[lane + 32 * i];
            sum = fmaf(cv.x, qv.x, sum);
            sum = fmaf(cv.y, qv.y, sum);
            sum = fmaf(cv.z, qv.z, sum);
            sum = fmaf(cv.w, qv.w, sum);
        }
#pragma unroll
        for (int off = 16; off; off >>= 1)
            sum += __shfl_down_sync(0xffffffffu, sum, off);
        if (lane == 0) sc[s] = sum;
    }
    __syncthreads();

    if (warp == 0) {
        float v0 = sc[lane], v1 = sc[lane + 32];
        float m = fmaxf(v0, v1);
#pragma unroll
        for (int off = 16; off; off >>= 1)
            m = fmaxf(m, __shfl_xor_sync(0xffffffffu, m, off));
        float e0 = __expf(v0 - m), e1 = __expf(v1 - m);
        float ssum = e0 + e1;
#pragma unroll
        for (int off = 16; off; off >>= 1)
            ssum += __shfl_xor_sync(0xffffffffu, ssum, off);
        float inv = 1.f / ssum;
        sc[lane] = e0 * inv;
        sc[lane + 32] = e1 * inv;
    }
    __syncthreads();

    float4 accv = make_float4(0.f, 0.f, 0.f, 0.f);
    for (int s = 0; s < S_; s++) {
        float a = sc[s];
        float4 cv = ((const float4*)(ctx + (size_t)(s * B_ + b) * D_))[tid];
        accv.x = fmaf(a, cv.x, accv.x);
        accv.y = fmaf(a, cv.y, accv.y);
        accv.z = fmaf(a, cv.z, accv.z);
        accv.w = fmaf(a, cv.w, accv.w);
    }
    ((float4*)(cat + (size_t)tb * 2 * D_))[tid] = accv;
    ((float4*)(cat + (size_t)tb * 2 * D_ + D_))[tid] =
        ((const float4*)(x + (size_t)tb * D_))[tid];

    if (t == T_ - 1 && tid < S_) attn_out[b * S_ + tid] = sc[tid];
}

// ---------------- launch ----------------
extern "C" void kernel_launch(void* const* d_in, const int* in_sizes, int n_in,
                              void* d_out, int out_size)
{
    (void)in_sizes; (void)n_in; (void)out_size;

    const int*   input = (const int*)  d_in[0];
    const float* h0    = (const float*)d_in[1];   // (L,B,D)
    const float* c0    = (const float*)d_in[2];   // (L,B,D)
    const float* ctx   = (const float*)d_in[3];   // (S,B,D)
    const float* emb   = (const float*)d_in[5];   // (V,D)
    const float* wih0  = (const float*)d_in[6];
    const float* whh0  = (const float*)d_in[7];
    const float* bih0  = (const float*)d_in[8];
    const float* bhh0  = (const float*)d_in[9];
    const float* wih1  = (const float*)d_in[10];
    const float* whh1  = (const float*)d_in[11];
    const float* bih1  = (const float*)d_in[12];
    const float* bhh1  = (const float*)d_in[13];
    const float* w_in  = (const float*)d_in[14];  // (D,D)
    const float* w_out = (const float*)d_in[15];  // (D,2D)

    float* out      = (float*)d_out;                       // (T,B,D)
    float* out_hn   = out + (size_t)TB_ * D_;              // (L,B,D)
    float* out_cn   = out_hn + (size_t)2 * B_ * D_;        // (L,B,D)
    float* out_attn = out_cn + (size_t)2 * B_ * D_;        // (B,S)

    float *x0, *xg, *x1, *x2, *c, *q, *cat;
    cudaGetSymbolAddress((void**)&x0,  g_x0);
    cudaGetSymbolAddress((void**)&xg,  g_xg);
    cudaGetSymbolAddress((void**)&x1,  g_x1);
    cudaGetSymbolAddress((void**)&x2,  g_x2);
    cudaGetSymbolAddress((void**)&c,   g_c);
    cudaGetSymbolAddress((void**)&q,   g_q);
    cudaGetSymbolAddress((void**)&cat, g_cat);

    const size_t BD = (size_t)B_ * D_;

    // 1) embedding
    embed_kernel<<<TB_, 256>>>(input, emb, x0);

    // 2) layer 0: input gates GEMM, then 32 recurrent steps
    sgemm_nt<1><<<dim3(D4_ / 128, TB_ / 128), 256>>>(
        x0, wih0, xg, TB_, D4_, D_, bih0, bhh0);
    cudaMemcpyAsync(c, c0, BD * sizeof(float), cudaMemcpyDeviceToDevice, 0);
    for (int t = 0; t < T_; t++) {
        const float* hprev = (t == 0) ? h0 : (x1 + (size_t)(t - 1) * BD);
        lstm_step<<<128, 256>>>(xg + (size_t)t * B_ * D4_, hprev, whh0,
                                c, x1 + (size_t)t * BD);
    }
    cudaMemcpyAsync(out_hn, x1 + (size_t)(T_ - 1) * BD, BD * sizeof(float),
                    cudaMemcpyDeviceToDevice, 0);
    cudaMemcpyAsync(out_cn, c, BD * sizeof(float), cudaMemcpyDeviceToDevice, 0);

    // 3) layer 1
    sgemm_nt<1><<<dim3(D4_ / 128, TB_ / 128), 256>>>(
        x1, wih1, xg, TB_, D4_, D_, bih1, bhh1);
    cudaMemcpyAsync(c, c0 + BD, BD * sizeof(float), cudaMemcpyDeviceToDevice, 0);
    for (int t = 0; t < T_; t++) {
        const float* hprev = (t == 0) ? (h0 + BD) : (x2 + (size_t)(t - 1) * BD);
        lstm_step<<<128, 256>>>(xg + (size_t)t * B_ * D4_, hprev, whh1,
                                c, x2 + (size_t)t * BD);
    }
    cudaMemcpyAsync(out_hn + BD, x2 + (size_t)(T_ - 1) * BD, BD * sizeof(float),
                    cudaMemcpyDeviceToDevice, 0);
    cudaMemcpyAsync(out_cn + BD, c, BD * sizeof(float), cudaMemcpyDeviceToDevice, 0);

    // 4) attention
    sgemm_nt<0><<<dim3(D_ / 128, TB_ / 128), 256>>>(
        x2, w_in, q, TB_, D_, D_, nullptr, nullptr);
    attn_kernel<<<dim3(B_, T_), 256>>>(q, ctx, x2, cat, out_attn);

    // 5) out = tanh(cat @ w_out^T)
    sgemm_nt<2><<<dim3(D_ / 128, TB_ / 128), 256>>>(
        cat, w_out, out, TB_, D_, 2 * D_, nullptr, nullptr);
}

// round 4
// speedup vs baseline: 1.3384x; 1.3384x over previous
#include <cuda_runtime.h>
#include <cuda_bf16.h>
#include <math.h>

#define T_ 32
#define B_ 64
#define S_ 64
#define D_ 1024
#define D4_ 4096
#define TB_ 2048

// ---------------- scratch (device globals) ----------------
__device__ float g_x0[TB_ * D_];
__device__ float g_xg[TB_ * D4_];
__device__ float g_x1[TB_ * D_];
__device__ float g_x2[TB_ * D_];
__device__ float g_c [B_ * D_];
__device__ float g_q [TB_ * D_];
__device__ float g_cat[TB_ * 2 * D_];

__device__ __align__(16) __nv_bfloat16 g_hb_hi[2][B_ * D_];
__device__ __align__(16) __nv_bfloat16 g_hb_lo[2][B_ * D_];
__device__ __align__(16) __nv_bfloat16 g_whi0[D4_ * D_];
__device__ __align__(16) __nv_bfloat16 g_wlo0[D4_ * D_];
__device__ __align__(16) __nv_bfloat16 g_whi1[D4_ * D_];
__device__ __align__(16) __nv_bfloat16 g_wlo1[D4_ * D_];

// ---------------- f32x2 helpers ----------------
__device__ __forceinline__ void fma2(unsigned long long& d,
                                     unsigned long long a,
                                     unsigned long long b)
{
    asm("fma.rn.f32x2 %0, %1, %2, %0;" : "+l"(d) : "l"(a), "l"(b));
}
__device__ __forceinline__ unsigned long long dup2(float a)
{
    unsigned long long r;
    asm("mov.b64 %0, {%1, %1};" : "=l"(r) : "r"(__float_as_uint(a)));
    return r;
}
__device__ __forceinline__ void unpack2(unsigned long long v, float& a, float& b)
{
    unsigned int lo, hi;
    asm("mov.b64 {%0, %1}, %2;" : "=r"(lo), "=r"(hi) : "l"(v));
    a = __uint_as_float(lo);
    b = __uint_as_float(hi);
}

// ---------------- mma helper ----------------
__device__ __forceinline__ void mma16816(float* d, const unsigned* a, const unsigned* b)
{
    asm volatile(
        "mma.sync.aligned.m16n8k16.row.col.f32.bf16.bf16.f32 "
        "{%0,%1,%2,%3}, {%4,%5,%6,%7}, {%8,%9}, {%0,%1,%2,%3};"
        : "+f"(d[0]), "+f"(d[1]), "+f"(d[2]), "+f"(d[3])
        : "r"(a[0]), "r"(a[1]), "r"(a[2]), "r"(a[3]),
          "r"(b[0]), "r"(b[1]));
}

// ---------------- embedding (padding_idx = 0) ----------------
__global__ void embed_kernel(const int* __restrict__ tok,
                             const float* __restrict__ emb,
                             float* __restrict__ x)
{
    int tb = blockIdx.x;
    int t4 = threadIdx.x;
    int tk = tok[tb];
    float4 v = make_float4(0.f, 0.f, 0.f, 0.f);
    if (tk != 0) v = ((const float4*)(emb + (size_t)tk * D_))[t4];
    ((float4*)(x + (size_t)tb * D_))[t4] = v;
}

// ---------------- split fp32 -> bf16 hi + lo ----------------
__global__ void split_kernel(const float* __restrict__ w,
                             __nv_bfloat16* __restrict__ hi,
                             __nv_bfloat16* __restrict__ lo, int n4)
{
    int i = blockIdx.x * blockDim.x + threadIdx.x;
    if (i >= n4) return;
    float4 v = ((const float4*)w)[i];
    float hx = __bfloat162float(__float2bfloat16(v.x));
    float hy = __bfloat162float(__float2bfloat16(v.y));
    float hz = __bfloat162float(__float2bfloat16(v.z));
    float hw = __bfloat162float(__float2bfloat16(v.w));
    __nv_bfloat162* hp = (__nv_bfloat162*)hi;
    __nv_bfloat162* lp = (__nv_bfloat162*)lo;
    hp[i * 2]     = __nv_bfloat162(__float2bfloat16(hx), __float2bfloat16(hy));
    hp[i * 2 + 1] = __nv_bfloat162(__float2bfloat16(hz), __float2bfloat16(hw));
    lp[i * 2]     = __nv_bfloat162(__float2bfloat16(v.x - hx), __float2bfloat16(v.y - hy));
    lp[i * 2 + 1] = __nv_bfloat162(__float2bfloat16(v.z - hz), __float2bfloat16(v.w - hw));
}

// ---------------- SGEMM: C = A @ B^T (+epilogue), f32x2 inner ----------------
template<int EPI>
__global__ __launch_bounds__(256)
void sgemm_nt(const float* __restrict__ A, const float* __restrict__ Bm,
              float* __restrict__ C, int M, int N, int K,
              const float* __restrict__ bias1, const float* __restrict__ bias2)
{
    __shared__ float As[16][128];
    __shared__ float Bs[16][128];

    const int tid = threadIdx.x;
    const int bm = blockIdx.y * 128;
    const int bn = blockIdx.x * 128;
    const int tx = tid & 15, ty = tid >> 4;

    unsigned long long acc[8][4];
#pragma unroll
    for (int i = 0; i < 8; i++)
#pragma unroll
        for (int j = 0; j < 4; j++) acc[i][j] = 0ULL;

    for (int k0 = 0; k0 < K; k0 += 16) {
#pragma unroll
        for (int i = 0; i < 2; i++) {
            int v = tid * 2 + i;
            int row = v >> 2;
            int q = (v & 3) * 4;
            float4 a4 = *(const float4*)(A + (size_t)(bm + row) * K + k0 + q);
            As[q + 0][row] = a4.x; As[q + 1][row] = a4.y;
            As[q + 2][row] = a4.z; As[q + 3][row] = a4.w;
            float4 b4 = *(const float4*)(Bm + (size_t)(bn + row) * K + k0 + q);
            Bs[q + 0][row] = b4.x; Bs[q + 1][row] = b4.y;
            Bs[q + 2][row] = b4.z; Bs[q + 3][row] = b4.w;
        }
        __syncthreads();

#pragma unroll
        for (int kk = 0; kk < 16; kk++) {
            float a[8];
            *(float4*)(a)     = *(const float4*)&As[kk][ty * 8];
            *(float4*)(a + 4) = *(const float4*)&As[kk][ty * 8 + 4];
            ulonglong2 bq0 = *(const ulonglong2*)&Bs[kk][tx * 8];
            ulonglong2 bq1 = *(const ulonglong2*)&Bs[kk][tx * 8 + 4];
#pragma unroll
            for (int i = 0; i < 8; i++) {
                unsigned long long ad = dup2(a[i]);
                fma2(acc[i][0], ad, bq0.x);
                fma2(acc[i][1], ad, bq0.y);
                fma2(acc[i][2], ad, bq1.x);
                fma2(acc[i][3], ad, bq1.y);
            }
        }
        __syncthreads();
    }

#pragma unroll
    for (int i = 0; i < 8; i++) {
        int m = bm + ty * 8 + i;
        int n0 = bn + tx * 8;
        float v[8];
#pragma unroll
        for (int p = 0; p < 4; p++) unpack2(acc[i][p], v[2 * p], v[2 * p + 1]);
#pragma unroll
        for (int j = 0; j < 8; j++) {
            float x = v[j];
            if (EPI == 1) x += bias1[n0 + j] + bias2[n0 + j];
            if (EPI == 2) x = tanhf(x);
            v[j] = x;
        }
        *(float4*)(C + (size_t)m * N + n0)     = *(float4*)(v);
        *(float4*)(C + (size_t)m * N + n0 + 4) = *(float4*)(v + 4);
    }
}

// ---------------- LSTM step via bf16 mma, 3-term split ----------------
// grid=128: block covers d = d0..d0+7 for all 4 gates, all 64 batches.
// 8 warps: warp w owns k in [w*128, w*128+128) for all 3 passes:
//   p0: h_hi * w_hi, p1: h_lo * w_hi, p2: h_hi * w_lo
// acc[mt][g][r] fp32 across all passes; tree-reduce over warps via smem;
// fused pointwise writes c, fp32 h, and next-step bf16 hi/lo h.
__global__ __launch_bounds__(256, 1)
void lstm_step_mma(const __nv_bfloat16* __restrict__ hA_hi,
                   const __nv_bfloat16* __restrict__ hA_lo,
                   const __nv_bfloat16* __restrict__ w_hi,
                   const __nv_bfloat16* __restrict__ w_lo,
                   const float* __restrict__ xg_t,   // (B, 4D)
                   float* __restrict__ c,            // (B, D)
                   float* __restrict__ hout,         // (B, D)
                   __nv_bfloat16* __restrict__ hN_hi,
                   __nv_bfloat16* __restrict__ hN_lo)
{
    __shared__ float red[4][2112];   // 33.8 KB: 4 reduce regions / gate stage

    const int tid  = threadIdx.x;
    const int wid  = tid >> 5;
    const int lane = tid & 31;
    const int gid  = lane >> 2;      // 0..7
    const int tig  = lane & 3;       // 0..3
    const int d0   = blockIdx.x << 3;

    float acc[4][4][4];              // [m-tile][gate][frag]
#pragma unroll
    for (int mt = 0; mt < 4; mt++)
#pragma unroll
        for (int g = 0; g < 4; g++)
#pragma unroll
            for (int r = 0; r < 4; r++) acc[mt][g][r] = 0.f;

    const unsigned* Hs[3] = { (const unsigned*)hA_hi, (const unsigned*)hA_lo,
                              (const unsigned*)hA_hi };
    const unsigned* Ws[3] = { (const unsigned*)w_hi, (const unsigned*)w_hi,
                              (const unsigned*)w_lo };
    const int kw = wid << 7;         // warp k-slice base

#pragma unroll
    for (int p = 0; p < 3; p++) {
        const unsigned* H = Hs[p];
        const unsigned* W = Ws[p];
#pragma unroll
        for (int s = 0; s < 8; s++) {
            const int kc = (kw + s * 16 + tig * 2) >> 1;  // u32 index within row
            unsigned a[4][4], b[4][2];
#pragma unroll
            for (int mt = 0; mt < 4; mt++) {
                int r0 = ((mt << 4) + gid) << 9;          // row * 512 u32
                a[mt][0] = __ldg(H + r0 + kc);
                a[mt][1] = __ldg(H + r0 + (8 << 9) + kc);
                a[mt][2] = __ldg(H + r0 + kc + 4);
                a[mt][3] = __ldg(H + r0 + (8 << 9) + kc + 4);
            }
#pragma unroll
            for (int g = 0; g < 4; g++) {
                int rn = ((g << 10) + d0 + gid) << 9;
                b[g][0] = __ldg(W + rn + kc);
                b[g][1] = __ldg(W + rn + kc + 4);
            }
#pragma unroll
            for (int mt = 0; mt < 4; mt++)
#pragma unroll
                for (int g = 0; g < 4; g++)
                    mma16816(acc[mt][g], a[mt], b[g]);
        }
    }

    // ---- tree reduction across 8 warps (k-slices) ----
    // round 1: warps 4-7 -> regions 0-3; warps 0-3 add
    if (wid >= 4) {
#pragma unroll
        for (int mt = 0; mt < 4; mt++)
#pragma unroll
            for (int g = 0; g < 4; g++)
#pragma unroll
                for (int r = 0; r < 4; r++)
                    red[wid - 4][((mt << 4) + (g << 2) + r) * 32 + lane] = acc[mt][g][r];
    }
    __syncthreads();
    if (wid < 4) {
#pragma unroll
        for (int mt = 0; mt < 4; mt++)
#pragma unroll
            for (int g = 0; g < 4; g++)
#pragma unroll
                for (int r = 0; r < 4; r++)
                    acc[mt][g][r] += red[wid][((mt << 4) + (g << 2) + r) * 32 + lane];
    }
    __syncthreads();
    // round 2
    if (wid == 2 || wid == 3) {
#pragma unroll
        for (int mt = 0; mt < 4; mt++)
#pragma unroll
            for (int g = 0; g < 4; g++)
#pragma unroll
                for (int r = 0; r < 4; r++)
                    red[wid - 2][((mt << 4) + (g << 2) + r) * 32 + lane] = acc[mt][g][r];
    }
    __syncthreads();
    if (wid < 2) {
#pragma unroll
        for (int mt = 0; mt < 4; mt++)
#pragma unroll
            for (int g = 0; g < 4; g++)
#pragma unroll
                for (int r = 0; r < 4; r++)
                    acc[mt][g][r] += red[wid][((mt << 4) + (g << 2) + r) * 32 + lane];
    }
    __syncthreads();
    // round 3
    if (wid == 1) {
#pragma unroll
        for (int mt = 0; mt < 4; mt++)
#pragma unroll
            for (int g = 0; g < 4; g++)
#pragma unroll
                for (int r = 0; r < 4; r++)
                    red[0][((mt << 4) + (g << 2) + r) * 32 + lane] = acc[mt][g][r];
    }
    __syncthreads();
    if (wid == 0) {
        // final sum + scatter gates into stage region red[2] (stride 33):
        // addr = b*33 + g*8 + dd,  b = mt*16 + gid + (r>=2)*8, dd = tig*2 + (r&1)
#pragma unroll
        for (int mt = 0; mt < 4; mt++)
#pragma unroll
            for (int g = 0; g < 4; g++)
#pragma unroll
                for (int r = 0; r < 4; r++) {
                    float v = acc[mt][g][r] + red[0][((mt << 4) + (g << 2) + r) * 32 + lane];
                    int b  = (mt << 4) + gid + ((r >> 1) << 3);
                    int dd = (tig << 1) + (r & 1);
                    red[2][b * 33 + (g << 3) + dd] = v;
                }
    }
    __syncthreads();

    // ---- pointwise: 512 (b,dd) pairs over 256 threads ----
#pragma unroll
    for (int j = 0; j < 2; j++) {
        int pid = tid + (j << 8);
        int b = pid >> 3, dd = pid & 7;
        int d = d0 + dd;
        float ig = red[2][b * 33 + 0 * 8 + dd] + xg_t[(size_t)b * D4_ + 0 * D_ + d];
        float fg = red[2][b * 33 + 1 * 8 + dd] + xg_t[(size_t)b * D4_ + 1 * D_ + d];
        float gg = red[2][b * 33 + 2 * 8 + dd] + xg_t[(size_t)b * D4_ + 2 * D_ + d];
        float og = red[2][b * 33 + 3 * 8 + dd] + xg_t[(size_t)b * D4_ + 3 * D_ + d];
        size_t idx = (size_t)b * D_ + d;
        float ci = c[idx];
        float i_ = 1.f / (1.f + __expf(-ig));
        float f_ = 1.f / (1.f + __expf(-fg));
        float o_ = 1.f / (1.f + __expf(-og));
        float cn = f_ * ci + i_ * tanhf(gg);
        float hn = o_ * tanhf(cn);
        c[idx] = cn;
        hout[idx] = hn;
        float hh = __bfloat162float(__float2bfloat16(hn));
        hN_hi[idx] = __float2bfloat16(hh);
        hN_lo[idx] = __float2bfloat16(hn - hh);
    }
}

// ---------------- attention ----------------
__global__ __launch_bounds__(256)
void attn_kernel(const float* __restrict__ q,
                 const float* __restrict__ ctx,
                 const float* __restrict__ x,
                 float* __restrict__ cat,
                 float* __restrict__ attn_out)
{
    const int b = blockIdx.x;
    const int t = blockIdx.y;
    const int tb = t * B_ + b;
    __shared__ float qs[D_];
    __shared__ float sc[S_];

    const int tid = threadIdx.x;
    const int warp = tid >> 5, lane = tid & 31;

    ((float4*)qs)[tid] = ((const float4*)(q + (size_t)tb * D_))[tid];
    __syncthreads();

#pragma unroll
    for (int si = 0; si < 8; si++) {
        int s = warp * 8 + si;
        const float4* crow = (const float4*)(ctx + (size_t)(s * B_ + b) * D_);
        float sum = 0.f;
#pragma unroll
        for (int i = 0; i < 8; i++) {
            float4 cv = crow[lane + 32 * i];
            float4 qv = ((const float4*)qs)[lane + 32 * i];
            sum = fmaf(cv.x, qv.x, sum);
            sum = fmaf(cv.y, qv.y, sum);
            sum = fmaf(cv.z, qv.z, sum);
            sum = fmaf(cv.w, qv.w, sum);
        }
#pragma unroll
        for (int off = 16; off; off >>= 1)
            sum += __shfl_down_sync(0xffffffffu, sum, off);
        if (lane == 0) sc[s] = sum;
    }
    __syncthreads();

    if (warp == 0) {
        float v0 = sc[lane], v1 = sc[lane + 32];
        float m = fmaxf(v0, v1);
#pragma unroll
        for (int off = 16; off; off >>= 1)
            m = fmaxf(m, __shfl_xor_sync(0xffffffffu, m, off));
        float e0 = __expf(v0 - m), e1 = __expf(v1 - m);
        float ssum = e0 + e1;
#pragma unroll
        for (int off = 16; off; off >>= 1)
            ssum += __shfl_xor_sync(0xffffffffu, ssum, off);
        float inv = 1.f / ssum;
        sc[lane] = e0 * inv;
        sc[lane + 32] = e1 * inv;
    }
    __syncthreads();

    float4 accv = make_float4(0.f, 0.f, 0.f, 0.f);
    for (int s = 0; s < S_; s++) {
        float a = sc[s];
        float4 cv = ((const float4*)(ctx + (size_t)(s * B_ + b) * D_))[tid];
        accv.x = fmaf(a, cv.x, accv.x);
        accv.y = fmaf(a, cv.y, accv.y);
        accv.z = fmaf(a, cv.z, accv.z);
        accv.w = fmaf(a, cv.w, accv.w);
    }
    ((float4*)(cat + (size_t)tb * 2 * D_))[tid] = accv;
    ((float4*)(cat + (size_t)tb * 2 * D_ + D_))[tid] =
        ((const float4*)(x + (size_t)tb * D_))[tid];

    if (t == T_ - 1 && tid < S_) attn_out[b * S_ + tid] = sc[tid];
}

// ---------------- launch ----------------
extern "C" void kernel_launch(void* const* d_in, const int* in_sizes, int n_in,
                              void* d_out, int out_size)
{
    (void)in_sizes; (void)n_in; (void)out_size;

    const int*   input = (const int*)  d_in[0];
    const float* h0    = (const float*)d_in[1];
    const float* c0    = (const float*)d_in[2];
    const float* ctx   = (const float*)d_in[3];
    const float* emb   = (const float*)d_in[5];
    const float* wih0  = (const float*)d_in[6];
    const float* whh0  = (const float*)d_in[7];
    const float* bih0  = (const float*)d_in[8];
    const float* bhh0  = (const float*)d_in[9];
    const float* wih1  = (const float*)d_in[10];
    const float* whh1  = (const float*)d_in[11];
    const float* bih1  = (const float*)d_in[12];
    const float* bhh1  = (const float*)d_in[13];
    const float* w_in  = (const float*)d_in[14];
    const float* w_out = (const float*)d_in[15];

    float* out      = (float*)d_out;
    float* out_hn   = out + (size_t)TB_ * D_;
    float* out_cn   = out_hn + (size_t)2 * B_ * D_;
    float* out_attn = out_cn + (size_t)2 * B_ * D_;

    float *x0, *xg, *x1, *x2, *c, *q, *cat;
    cudaGetSymbolAddress((void**)&x0,  g_x0);
    cudaGetSymbolAddress((void**)&xg,  g_xg);
    cudaGetSymbolAddress((void**)&x1,  g_x1);
    cudaGetSymbolAddress((void**)&x2,  g_x2);
    cudaGetSymbolAddress((void**)&c,   g_c);
    cudaGetSymbolAddress((void**)&q,   g_q);
    cudaGetSymbolAddress((void**)&cat, g_cat);

    __nv_bfloat16 *hbh, *hbl, *whi0, *wlo0, *whi1, *wlo1;
    cudaGetSymbolAddress((void**)&hbh,  g_hb_hi);
    cudaGetSymbolAddress((void**)&hbl,  g_hb_lo);
    cudaGetSymbolAddress((void**)&whi0, g_whi0);
    cudaGetSymbolAddress((void**)&wlo0, g_wlo0);
    cudaGetSymbolAddress((void**)&whi1, g_whi1);
    cudaGetSymbolAddress((void**)&wlo1, g_wlo1);

    const size_t BD = (size_t)B_ * D_;

    // 0) weight splits (bf16 hi/lo)
    split_kernel<<<4096, 256>>>(whh0, whi0, wlo0, D4_ * D_ / 4);
    split_kernel<<<4096, 256>>>(whh1, whi1, wlo1, D4_ * D_ / 4);

    // 1) embedding
    embed_kernel<<<TB_, 256>>>(input, emb, x0);

    // 2) layer 0
    sgemm_nt<1><<<dim3(D4_ / 128, TB_ / 128), 256>>>(
        x0, wih0, xg, TB_, D4_, D_, bih0, bhh0);
    split_kernel<<<64, 256>>>(h0, hbh, hbl, (int)(BD / 4));   // h -> buf[0]
    cudaMemcpyAsync(c, c0, BD * sizeof(float), cudaMemcpyDeviceToDevice, 0);
    for (int t = 0; t < T_; t++) {
        int cur = t & 1, nxt = (t + 1) & 1;
        lstm_step_mma<<<128, 256>>>(hbh + (size_t)cur * BD, hbl + (size_t)cur * BD,
                                    whi0, wlo0,
                                    xg + (size_t)t * B_ * D4_, c,
                                    x1 + (size_t)t * BD,
                                    hbh + (size_t)nxt * BD, hbl + (size_t)nxt * BD);
    }
    cudaMemcpyAsync(out_hn, x1 + (size_t)(T_ - 1) * BD, BD * sizeof(float),
                    cudaMemcpyDeviceToDevice, 0);
    cudaMemcpyAsync(out_cn, c, BD * sizeof(float), cudaMemcpyDeviceToDevice, 0);

    // 3) layer 1
    sgemm_nt<1><<<dim3(D4_ / 128, TB_ / 128), 256>>>(
        x1, wih1, xg, TB_, D4_, D_, bih1, bhh1);
    split_kernel<<<64, 256>>>(h0 + BD, hbh, hbl, (int)(BD / 4));
    cudaMemcpyAsync(c, c0 + BD, BD * sizeof(float), cudaMemcpyDeviceToDevice, 0);
    for (int t = 0; t < T_; t++) {
        int cur = t & 1, nxt = (t + 1) & 1;
        lstm_step_mma<<<128, 256>>>(hbh + (size_t)cur * BD, hbl + (size_t)cur * BD,
                                    whi1, wlo1,
                                    xg + (size_t)t * B_ * D4_, c,
                                    x2 + (size_t)t * BD,
                                    hbh + (size_t)nxt * BD, hbl + (size_t)nxt * BD);
    }
    cudaMemcpyAsync(out_hn + BD, x2 + (size_t)(T_ - 1) * BD, BD * sizeof(float),
                    cudaMemcpyDeviceToDevice, 0);
    cudaMemcpyAsync(out_cn + BD, c, BD * sizeof(float), cudaMemcpyDeviceToDevice, 0);

    // 4) attention
    sgemm_nt<0><<<dim3(D_ / 128, TB_ / 128), 256>>>(
        x2, w_in, q, TB_, D_, D_, nullptr, nullptr);
    attn_kernel<<<dim3(B_, T_), 256>>>(q, ctx, x2, cat, out_attn);

    // 5) out = tanh(cat @ w_out^T)
    sgemm_nt<2><<<dim3(D_ / 128, TB_ / 128), 256>>>(
        cat, w_out, out, TB_, D_, 2 * D_, nullptr, nullptr);
}